// round 7
// baseline (speedup 1.0000x reference)
#include <cuda_runtime.h>
#include <cstdint>

#define NN   50000
#define BB   2
#define FIN  128
#define FOUT 64
#define OC   128          // B*FOUT = gather row width = concatenated weight cols
#define EE   800000
#define ROWS (BB * NN)    // 100000

#define WPAD 130                       // padded f-stride for transposed W (conflict-free LDS.64)
#define SMEM_W_FLOATS (OC * WPAD)      // 16640
#define SMEM_X_FLOATS (64 * FIN)       // 8192
#define SMEM_BYTES ((SMEM_W_FLOATS + SMEM_X_FLOATS) * 4)   // 99328

// Scratch (allocation-free rule: __device__ globals)
__device__ float g_xt[NN * OC];   // x@W laid out as (n, b*FOUT + o)  -- gather source
__device__ float g_agg[NN * OC];  // scatter destination

// ---------------------------------------------------------------------------
// Fused GEMM, f-paired packed-fp32 variant.
// Block = 256 threads (8 warps), 64 rows/block (8 rows/warp).
// smem: wsT[c][f] transposed combined weights (c<64: W, c>=64: Wself), pad 130
//       xs[r][f]  block's x tile, staged coalesced.
// Lane owns 4 columns c_k = k*32 + lane. Each 64-bit acc = {sum even f, sum odd f}
// of one column: x pair comes packed from the float4 (no movs), W pair comes
// packed from transposed smem (LDS.64, conflict-free by 130-pad).
// ---------------------------------------------------------------------------
__global__ __launch_bounds__(256, 1) void gemm_kernel(
    const float* __restrict__ x, const float* __restrict__ W,
    const float* __restrict__ Wself, const float* __restrict__ bself,
    float* __restrict__ out)
{
    extern __shared__ float sm[];
    float* wsT = sm;                       // [OC][WPAD]
    float* xs  = sm + SMEM_W_FLOATS;       // [64][FIN]

    const int t = threadIdx.x;
    const long rb = (long)blockIdx.x * 64; // block row base

    // Stage combined W transposed: wsT[cc*WPAD + f] = (cc<64 ? W : Wself)[f][cc%64]
    for (int idx = t; idx < FIN * OC; idx += 256) {
        int f = idx >> 7, cc = idx & 127;
        float v = (cc < 64) ? W[(f << 6) + cc] : Wself[(f << 6) + (cc - 64)];
        wsT[cc * WPAD + f] = v;
    }
    // Stage x tile coalesced: 64 rows x 128 f = 2048 float4 slots
    for (int idx = t; idx < 64 * 32; idx += 256) {
        int r = idx >> 5, q = idx & 31;
        long g = rb + r;
        float4 v = (g < ROWS) ? *(const float4*)(x + g * FIN + q * 4)
                              : make_float4(0.f, 0.f, 0.f, 0.f);
        *(float4*)(xs + r * FIN + q * 4) = v;
    }
    __syncthreads();

    const int lane  = t & 31;
    const int wrow0 = (t >> 5) * 8;        // warp's local row base (0..56)
    const float* xsp = xs + wrow0 * FIN;

    unsigned long long acc[8][4];
    #pragma unroll
    for (int i = 0; i < 8; i++)
        #pragma unroll
        for (int k = 0; k < 4; k++) acc[i][k] = 0ull;

    // per-lane W pointers for the 4 owned columns
    const float* wp0 = wsT + (0 * 32 + lane) * WPAD;
    const float* wp1 = wsT + (1 * 32 + lane) * WPAD;
    const float* wp2 = wsT + (2 * 32 + lane) * WPAD;
    const float* wp3 = wsT + (3 * 32 + lane) * WPAD;

    #pragma unroll 4
    for (int f = 0; f < FIN; f += 4) {
        // x: 8 rows, 4 consecutive f = two packed f-pairs per row (no movs)
        ulonglong2 xq[8];
        #pragma unroll
        for (int i = 0; i < 8; i++)
            xq[i] = *(const ulonglong2*)(xsp + i * FIN + f);   // broadcast LDS.128

        // w: 4 columns x two packed f-pairs (conflict-free LDS.64)
        unsigned long long wA[4], wB[4];
        wA[0] = *(const unsigned long long*)(wp0 + f);
        wA[1] = *(const unsigned long long*)(wp1 + f);
        wA[2] = *(const unsigned long long*)(wp2 + f);
        wA[3] = *(const unsigned long long*)(wp3 + f);
        wB[0] = *(const unsigned long long*)(wp0 + f + 2);
        wB[1] = *(const unsigned long long*)(wp1 + f + 2);
        wB[2] = *(const unsigned long long*)(wp2 + f + 2);
        wB[3] = *(const unsigned long long*)(wp3 + f + 2);

        #pragma unroll
        for (int i = 0; i < 8; i++) {
            #pragma unroll
            for (int k = 0; k < 4; k++) {
                asm("fma.rn.f32x2 %0, %1, %2, %0;" : "+l"(acc[i][k]) : "l"(xq[i].x), "l"(wA[k]));
                asm("fma.rn.f32x2 %0, %1, %2, %0;" : "+l"(acc[i][k]) : "l"(xq[i].y), "l"(wB[k]));
            }
        }
    }

    // Epilogue: fold even/odd halves, route cols 0..63 -> g_xt, 64..127 -> out(+bias)
    const float bias0 = bself[lane];
    const float bias1 = bself[32 + lane];
    #pragma unroll
    for (int i = 0; i < 8; i++) {
        long g = rb + wrow0 + i;
        if (g >= ROWS) break;
        int b = (int)(g / NN);
        int n = (int)(g % NN);
        float* xtp  = g_xt + (long)n * OC + b * FOUT;
        float* outp = out + g * FOUT;
        #pragma unroll
        for (int k = 0; k < 4; k++) {
            float lo, hi;
            asm("mov.b64 {%0, %1}, %2;" : "=f"(lo), "=f"(hi) : "l"(acc[i][k]));
            float s = lo + hi;
            int c = k * 32 + lane;
            if (c < 64) {
                xtp[c] = s;                                    // W path -> gather source
            } else {
                outp[c - 64] = s + ((k == 2) ? bias0 : bias1); // Wself path + bias
            }
        }
    }
}

// ---------------------------------------------------------------------------
// Edge scatter: one warp per edge. Lane l handles floats [4l,4l+4) of the
// 128-float row. Vector RED (red.global.add.v4.f32) quarters atomic op count.
// ---------------------------------------------------------------------------
__global__ __launch_bounds__(256) void scatter_kernel(
    const int* __restrict__ erow, const int* __restrict__ ecol,
    const float* __restrict__ eval)
{
    int e = blockIdx.x * 8 + (threadIdx.x >> 5);   // 800000 / 8 = 100000 blocks, exact
    int lane = threadIdx.x & 31;
    int r = erow[e], c = ecol[e];
    float v = eval[e];
    float4 s = *(const float4*)(g_xt + (long)c * OC + lane * 4);
    float* dst = g_agg + (long)r * OC + lane * 4;
    asm volatile("red.global.add.v4.f32 [%0], {%1, %2, %3, %4};"
                 :: "l"(dst), "f"(s.x * v), "f"(s.y * v), "f"(s.z * v), "f"(s.w * v)
                 : "memory");
}

// ---------------------------------------------------------------------------
// Epilogue: out[b][n][o] = relu(out[b][n][o] + agg[n][b*64+o])
// ---------------------------------------------------------------------------
__global__ __launch_bounds__(256) void epilogue_kernel(float* __restrict__ out)
{
    long i = (long)blockIdx.x * 256 + threadIdx.x;   // 1.6M float4 units, exact grid
    int  o4   = (int)(i & 15) * 4;
    long rest = i >> 4;                              // b*NN + n
    int  n = (int)(rest % NN);
    int  b = (int)(rest / NN);
    float4 a = *(const float4*)(g_agg + (long)n * OC + b * FOUT + o4);
    float4 s = *(float4*)(out + i * 4);
    s.x = fmaxf(s.x + a.x, 0.f);
    s.y = fmaxf(s.y + a.y, 0.f);
    s.z = fmaxf(s.z + a.z, 0.f);
    s.w = fmaxf(s.w + a.w, 0.f);
    *(float4*)(out + i * 4) = s;
}

extern "C" void kernel_launch(void* const* d_in, const int* in_sizes, int n_in,
                              void* d_out, int out_size)
{
    const float* x     = (const float*)d_in[0];
    const float* W     = (const float*)d_in[1];
    const float* Wself = (const float*)d_in[2];
    const float* bself = (const float*)d_in[3];
    const int*   erow  = (const int*)d_in[4];
    const int*   ecol  = (const int*)d_in[5];
    const float* eval  = (const float*)d_in[6];
    float* out = (float*)d_out;

    void* aggp = nullptr;
    cudaGetSymbolAddress(&aggp, g_agg);
    cudaMemsetAsync(aggp, 0, (size_t)NN * OC * sizeof(float), 0);

    cudaFuncSetAttribute(gemm_kernel, cudaFuncAttributeMaxDynamicSharedMemorySize, SMEM_BYTES);
    gemm_kernel<<<(ROWS + 63) / 64, 256, SMEM_BYTES>>>(x, W, Wself, bself, out);  // 1563 blocks

    scatter_kernel<<<EE / 8, 256>>>(erow, ecol, eval);                 // 100000 blocks

    epilogue_kernel<<<(long)BB * NN * FOUT / 4 / 256, 256>>>(out);     // 6250 blocks
}